// round 1
// baseline (speedup 1.0000x reference)
#include <cuda_runtime.h>
#include <cstdint>

#define L_DIM 2048
#define D_DIM 64
#define N_BH 32
#define ROWS 128
#define JT 128
#define NTHREADS 256
#define PITCH 132              // floats; 132*4=528B keeps 16B alignment per kk row
#define NJT (L_DIM / JT)

typedef unsigned long long ull;

__device__ __forceinline__ ull pack2(float lo, float hi) {
    ull r;
    asm("mov.b64 %0, {%1, %2};" : "=l"(r) : "r"(__float_as_uint(lo)), "r"(__float_as_uint(hi)));
    return r;
}
__device__ __forceinline__ void unpack2(ull v, float& lo, float& hi) {
    unsigned int a, b;
    asm("mov.b64 {%0, %1}, %2;" : "=r"(a), "=r"(b) : "l"(v));
    lo = __uint_as_float(a);
    hi = __uint_as_float(b);
}
__device__ __forceinline__ ull fma2(ull a, ull b, ull c) {
    ull d;
    asm("fma.rn.f32x2 %0, %1, %2, %3;" : "=l"(d) : "l"(a), "l"(b), "l"(c));
    return d;
}

// (relu(a)+1e-12)^(2/3) without MUFU: rcbrt bit-hack seed + 2 Newton iters
// w ~ x^(-1/3); w' = w*(4 - x*w^3)/3  (multiply-only); y = x*w' = t*u
__device__ __forceinline__ float pow23(float a) {
    float x = fmaxf(a, 0.0f) + 1e-12f;
    float w = __int_as_float(0x54A2FC96 - (__float_as_int(x) / 3));
    // Newton 1
    float t = x * w;
    float u = fmaf(-(1.0f / 3.0f), t * w * w, 4.0f / 3.0f);
    w = w * u;
    // Newton 2
    t = x * w;
    u = fmaf(-(1.0f / 3.0f), t * w * w, 4.0f / 3.0f);
    return t * u;   // = x * w_refined = x^(2/3)
}

__global__ void __launch_bounds__(NTHREADS, 2)
fused_affinity_cumsum(const float* __restrict__ kin,
                      const float* __restrict__ src,
                      const float* __restrict__ dst,
                      float* __restrict__ out)
{
    extern __shared__ float smem[];
    float* kis = smem;                       // [D_DIM][PITCH] : Ki^T * sqrt(src)
    float* kjs = smem + D_DIM * PITCH;       // [D_DIM][PITCH] : Kj^T * sqrt(dest)

    const int bh  = blockIdx.y;
    const int i0  = blockIdx.x * ROWS;
    const int tid = threadIdx.x;
    const int tr  = tid >> 4;    // 0..15 -> rows tr*8..tr*8+7
    const int tc  = tid & 15;    // 0..15 -> cols tc*8..tc*8+7
    const int lane = tid & 31;

    const float* kb = kin + (size_t)bh * (L_DIM * D_DIM);
    const float* sb = src + bh * L_DIM;
    const float* db = dst + bh * L_DIM;

    // Load Ki tile [128 x 64], scale rows by sqrt(src+eps), store transposed.
    #pragma unroll
    for (int t = 0; t < 8; ++t) {
        int idx = tid + t * NTHREADS;          // 0..2047
        int row = idx >> 4;                    // 0..127
        int seg = idx & 15;                    // 0..15 (float4 segment)
        float4 v = *(const float4*)(kb + (size_t)(i0 + row) * D_DIM + seg * 4);
        float s = sqrtf(sb[i0 + row] + 1e-12f);
        kis[(seg * 4 + 0) * PITCH + row] = v.x * s;
        kis[(seg * 4 + 1) * PITCH + row] = v.y * s;
        kis[(seg * 4 + 2) * PITCH + row] = v.z * s;
        kis[(seg * 4 + 3) * PITCH + row] = v.w * s;
    }

    float carry[8];
    #pragma unroll
    for (int r = 0; r < 8; ++r) carry[r] = 0.0f;

    const int irow0 = i0 + tr * 8;
    float* outrow = out + ((size_t)bh * L_DIM + irow0) * L_DIM;

    for (int jt = 0; jt < NJT; ++jt) {
        __syncthreads();   // prior tile's readers done before overwriting kjs
        #pragma unroll
        for (int t = 0; t < 8; ++t) {
            int idx = tid + t * NTHREADS;
            int row = idx >> 4;
            int seg = idx & 15;
            int j = jt * JT + row;
            float4 v = *(const float4*)(kb + (size_t)j * D_DIM + seg * 4);
            float d = sqrtf(db[j] + 1e-12f);
            kjs[(seg * 4 + 0) * PITCH + row] = v.x * d;
            kjs[(seg * 4 + 1) * PITCH + row] = v.y * d;
            kjs[(seg * 4 + 2) * PITCH + row] = v.z * d;
            kjs[(seg * 4 + 3) * PITCH + row] = v.w * d;
        }
        __syncthreads();

        // 8x8 micro-tile GEMM over k=64, accumulators packed as row-pairs (f32x2)
        ull acc2[4][8];
        #pragma unroll
        for (int p = 0; p < 4; ++p)
            #pragma unroll
            for (int c = 0; c < 8; ++c) acc2[p][c] = 0ull;

        const float* arow = kis + tr * 8;
        const float* brow = kjs + tc * 8;
        #pragma unroll 8
        for (int kk = 0; kk < D_DIM; ++kk) {
            // a: 8 consecutive rows -> 4 natural f32x2 pairs (16B aligned)
            ulonglong2 Alo = *(const ulonglong2*)(arow + kk * PITCH);
            ulonglong2 Ahi = *(const ulonglong2*)(arow + kk * PITCH + 4);
            float4 b0 = *(const float4*)(brow + kk * PITCH);
            float4 b1 = *(const float4*)(brow + kk * PITCH + 4);
            ull ap[4] = {Alo.x, Alo.y, Ahi.x, Ahi.y};
            ull bd[8];
            bd[0] = pack2(b0.x, b0.x);
            bd[1] = pack2(b0.y, b0.y);
            bd[2] = pack2(b0.z, b0.z);
            bd[3] = pack2(b0.w, b0.w);
            bd[4] = pack2(b1.x, b1.x);
            bd[5] = pack2(b1.y, b1.y);
            bd[6] = pack2(b1.z, b1.z);
            bd[7] = pack2(b1.w, b1.w);
            #pragma unroll
            for (int p = 0; p < 4; ++p)
                #pragma unroll
                for (int c = 0; c < 8; ++c)
                    acc2[p][c] = fma2(ap[p], bd[c], acc2[p][c]);
        }

        // Epilogue per row-pair: pow(2/3), row cumsum (thread prefix + 16-lane
        // scan + cross-tile carry), causal mask, vectorized store.
        const int jb = jt * JT + tc * 8;
        #pragma unroll
        for (int p = 0; p < 4; ++p) {
            float v[2][8];
            #pragma unroll
            for (int c = 0; c < 8; ++c) {
                float lo, hi;
                unpack2(acc2[p][c], lo, hi);
                v[0][c] = pow23(lo);
                v[1][c] = pow23(hi);
            }
            #pragma unroll
            for (int h = 0; h < 2; ++h) {
                const int rr = p * 2 + h;
                #pragma unroll
                for (int c = 1; c < 8; ++c) v[h][c] += v[h][c - 1];
                float tot = v[h][7];
                float sc = tot;
                #pragma unroll
                for (int off = 1; off < 16; off <<= 1) {
                    float u = __shfl_up_sync(0xffffffffu, sc, off, 16);
                    if ((lane & 15) >= off) sc += u;
                }
                float base = carry[rr] + (sc - tot);             // exclusive + carry
                carry[rr] += __shfl_sync(0xffffffffu, sc, 15, 16); // tile total
                const int i = irow0 + rr;
                float4 o0, o1;
                o0.x = (jb + 0 >= i) ? v[h][0] + base : 0.0f;
                o0.y = (jb + 1 >= i) ? v[h][1] + base : 0.0f;
                o0.z = (jb + 2 >= i) ? v[h][2] + base : 0.0f;
                o0.w = (jb + 3 >= i) ? v[h][3] + base : 0.0f;
                o1.x = (jb + 4 >= i) ? v[h][4] + base : 0.0f;
                o1.y = (jb + 5 >= i) ? v[h][5] + base : 0.0f;
                o1.z = (jb + 6 >= i) ? v[h][6] + base : 0.0f;
                o1.w = (jb + 7 >= i) ? v[h][7] + base : 0.0f;
                float* op = outrow + (size_t)rr * L_DIM + jb;
                *(float4*)op       = o0;
                *(float4*)(op + 4) = o1;
            }
        }
    }
}

extern "C" void kernel_launch(void* const* d_in, const int* in_sizes, int n_in,
                              void* d_out, int out_size) {
    const float* k    = (const float*)d_in[0];
    const float* src  = (const float*)d_in[1];
    const float* dest = (const float*)d_in[2];
    float* out = (float*)d_out;

    const int smem_bytes = 2 * D_DIM * PITCH * (int)sizeof(float);   // 67,584 B
    cudaFuncSetAttribute(fused_affinity_cumsum,
                         cudaFuncAttributeMaxDynamicSharedMemorySize, smem_bytes);

    dim3 grid(L_DIM / ROWS, N_BH);   // 16 x 32 = 512 CTAs
    fused_affinity_cumsum<<<grid, NTHREADS, smem_bytes>>>(k, src, dest, out);
}

// round 3
// speedup vs baseline: 1.9319x; 1.9319x over previous
#include <cuda_runtime.h>
#include <cuda_bf16.h>
#include <cstdint>

#define L_DIM 2048
#define D_DIM 64
#define ROWS 128
#define JT 128
#define NJT 16
#define NTH 256

// SMEM layout (bytes): four 128x64 bf16 tiles, 16KB each
#define OFF_AH 0
#define OFF_AL 16384
#define OFF_BH 32768
#define OFF_BL 49152
#define SMEM_TOTAL 65536

__device__ __forceinline__ uint32_t smem_u32(const void* p) {
    uint32_t a;
    asm("{ .reg .u64 t; cvta.to.shared.u64 t, %1; cvt.u32.u64 %0, t; }" : "=r"(a) : "l"(p));
    return a;
}
__device__ __forceinline__ int swz(int x) { return x ^ ((x >> 3) & 0x70); }

__device__ __forceinline__ float lg2f(float x) {
    float y; asm("lg2.approx.f32 %0, %1;" : "=f"(y) : "f"(x)); return y;
}
__device__ __forceinline__ float ex2f(float x) {
    float y; asm("ex2.approx.f32 %0, %1;" : "=f"(y) : "f"(x)); return y;
}
// (relu(a)+1e-12)^(2/3) on the MUFU pipe
__device__ __forceinline__ float pow23(float a) {
    float x = fmaxf(a, 0.0f) + 1e-12f;
    return ex2f(lg2f(x) * 0.666666667f);
}

__device__ __forceinline__ void ldsm4(uint32_t* r, uint32_t addr) {
    asm volatile("ldmatrix.sync.aligned.m8n8.x4.shared.b16 {%0,%1,%2,%3}, [%4];"
                 : "=r"(r[0]), "=r"(r[1]), "=r"(r[2]), "=r"(r[3]) : "r"(addr));
}
__device__ __forceinline__ void mma16816(float* c, const uint32_t* a, const uint32_t* b) {
    asm volatile(
        "mma.sync.aligned.m16n8k16.row.col.f32.bf16.bf16.f32 "
        "{%0,%1,%2,%3}, {%4,%5,%6,%7}, {%8,%9}, {%0,%1,%2,%3};"
        : "+f"(c[0]), "+f"(c[1]), "+f"(c[2]), "+f"(c[3])
        : "r"(a[0]), "r"(a[1]), "r"(a[2]), "r"(a[3]), "r"(b[0]), "r"(b[1]));
}

// Convert 128x64 fp32 rows (scaled by sqrt(w+eps)) -> bf16 hi + bf16 residual
// tiles in SMEM, SW128 swizzled (128B per row).
__device__ __forceinline__ void cvt_tile(const float* __restrict__ krows,
                                         const float* __restrict__ w,
                                         char* smem, int off_hi, int off_lo, int tid)
{
    #pragma unroll
    for (int it = 0; it < (ROWS * 16) / NTH; ++it) {
        int idx = tid + it * NTH;
        int row = idx >> 4;
        int seg = idx & 15;
        float4 v = *(const float4*)(krows + row * D_DIM + seg * 4);
        float s = sqrtf(w[row] + 1e-12f);
        float x0 = v.x * s, x1 = v.y * s, x2 = v.z * s, x3 = v.w * s;
        __nv_bfloat16 h0 = __float2bfloat16(x0), h1 = __float2bfloat16(x1);
        __nv_bfloat16 h2 = __float2bfloat16(x2), h3 = __float2bfloat16(x3);
        __nv_bfloat16 l0 = __float2bfloat16(x0 - __bfloat162float(h0));
        __nv_bfloat16 l1 = __float2bfloat16(x1 - __bfloat162float(h1));
        __nv_bfloat16 l2 = __float2bfloat16(x2 - __bfloat162float(h2));
        __nv_bfloat16 l3 = __float2bfloat16(x3 - __bfloat162float(h3));
        __nv_bfloat162 hA = __halves2bfloat162(h0, h1), hB = __halves2bfloat162(h2, h3);
        __nv_bfloat162 lA = __halves2bfloat162(l0, l1), lB = __halves2bfloat162(l2, l3);
        int sw = swz(row * 128 + seg * 8);
        *(uint2*)(smem + off_hi + sw) = make_uint2(*(const unsigned*)&hA, *(const unsigned*)&hB);
        *(uint2*)(smem + off_lo + sw) = make_uint2(*(const unsigned*)&lA, *(const unsigned*)&lB);
    }
}

__global__ void __launch_bounds__(NTH, 2)
mha_hmma_kernel(const float* __restrict__ kin, const float* __restrict__ src,
                const float* __restrict__ dst, float* __restrict__ out)
{
    extern __shared__ char smem[];
    const uint32_t sbase = smem_u32(smem);
    const int tid = threadIdx.x;
    const int warp = tid >> 5;
    const int lane = tid & 31;
    const int bh = blockIdx.y;
    const int i0 = blockIdx.x * ROWS;

    const float* kb = kin + (size_t)bh * (L_DIM * D_DIM);
    const float* sb = src + bh * L_DIM;
    const float* db = dst + bh * L_DIM;

    // A tile: rows i0..i0+127 scaled by sqrt(src+eps); converted once.
    cvt_tile(kb + (size_t)i0 * D_DIM, sb + i0, smem, OFF_AH, OFF_AL, tid);

    // ldmatrix lane address components
    // A fragment (m16k16): m0 rows0-7 k0-7 | m1 rows8-15 k0-7 | m2 rows0-7 k8-15 | m3 rows8-15 k8-15
    const int a_row = warp * 16 + ((lane >> 3) & 1) * 8 + (lane & 7);
    const int a_kb  = ((lane >> 4) & 1) * 16;
    // B fragment (two n8 x k16 tiles): m0 n0-7 k0-7 | m1 n0-7 k8-15 | m2 n8-15 k0-7 | m3 n8-15 k8-15
    const int b_nrow = ((lane >> 4) & 1) * 8 + (lane & 7);
    const int b_kb   = ((lane >> 3) & 1) * 16;

    const int q = lane & 3;
    const int i_up = i0 + warp * 16 + (lane >> 2);
    const int i_dn = i_up + 8;
    float* orow_up = out + ((size_t)bh * L_DIM + i_up) * L_DIM;
    float* orow_dn = orow_up + 8 * L_DIM;

    float carry_up = 0.0f, carry_dn = 0.0f;

    for (int jt = 0; jt < NJT; ++jt) {
        __syncthreads();   // prior tile's ldmatrix readers done before B overwrite
        cvt_tile(kb + (size_t)(jt * JT) * D_DIM, db + jt * JT, smem, OFF_BH, OFF_BL, tid);
        __syncthreads();

        float acc[16][4];
        #pragma unroll
        for (int n = 0; n < 16; ++n)
            #pragma unroll
            for (int c = 0; c < 4; ++c) acc[n][c] = 0.0f;

        #pragma unroll
        for (int ks = 0; ks < 4; ++ks) {
            const int aoff = swz(a_row * 128 + ks * 32 + a_kb);
            uint32_t ah[4], al[4];
            ldsm4(ah, sbase + OFF_AH + aoff);
            ldsm4(al, sbase + OFF_AL + aoff);
            #pragma unroll
            for (int nb2 = 0; nb2 < 8; ++nb2) {
                const int boff = swz((nb2 * 16 + b_nrow) * 128 + ks * 32 + b_kb);
                uint32_t bhr[4], blr[4];
                ldsm4(bhr, sbase + OFF_BH + boff);
                ldsm4(blr, sbase + OFF_BL + boff);
                mma16816(acc[2 * nb2],     ah, bhr);
                mma16816(acc[2 * nb2 + 1], ah, bhr + 2);
                mma16816(acc[2 * nb2],     al, bhr);
                mma16816(acc[2 * nb2 + 1], al, bhr + 2);
                mma16816(acc[2 * nb2],     ah, blr);
                mma16816(acc[2 * nb2 + 1], ah, blr + 2);
            }
        }

        // Epilogue: pow(2/3) on MUFU, pairwise + 4-lane scan cumsum, causal mask, store.
        #pragma unroll
        for (int nb = 0; nb < 16; ++nb) {
            const int j0 = jt * JT + nb * 8 + q * 2;
            {   // rows lane>>2 (upper half of m16)
                float y0 = pow23(acc[nb][0]);
                float y1 = pow23(acc[nb][1]);
                float v = y0 + y1;
                float s = v;
                float u1 = __shfl_up_sync(0xffffffffu, s, 1, 4); if (q >= 1) s += u1;
                float u2 = __shfl_up_sync(0xffffffffu, s, 2, 4); if (q >= 2) s += u2;
                float tot = __shfl_sync(0xffffffffu, s, 3, 4);
                float base = carry_up + (s - v);
                float2 o;
                o.x = (j0     >= i_up) ? base + y0 : 0.0f;
                o.y = (j0 + 1 >= i_up) ? base + v  : 0.0f;
                *(float2*)(orow_up + j0) = o;
                carry_up += tot;
            }
            {   // rows (lane>>2)+8
                float y0 = pow23(acc[nb][2]);
                float y1 = pow23(acc[nb][3]);
                float v = y0 + y1;
                float s = v;
                float u1 = __shfl_up_sync(0xffffffffu, s, 1, 4); if (q >= 1) s += u1;
                float u2 = __shfl_up_sync(0xffffffffu, s, 2, 4); if (q >= 2) s += u2;
                float tot = __shfl_sync(0xffffffffu, s, 3, 4);
                float base = carry_dn + (s - v);
                float2 o;
                o.x = (j0     >= i_dn) ? base + y0 : 0.0f;
                o.y = (j0 + 1 >= i_dn) ? base + v  : 0.0f;
                *(float2*)(orow_dn + j0) = o;
                carry_dn += tot;
            }
        }
    }
}

extern "C" void kernel_launch(void* const* d_in, const int* in_sizes, int n_in,
                              void* d_out, int out_size) {
    const float* k    = (const float*)d_in[0];
    const float* src  = (const float*)d_in[1];
    const float* dest = (const float*)d_in[2];
    float* out = (float*)d_out;

    cudaFuncSetAttribute(mha_hmma_kernel,
                         cudaFuncAttributeMaxDynamicSharedMemorySize, SMEM_TOTAL);

    dim3 grid(L_DIM / ROWS, 32);   // 16 i-tiles x 32 bh = 512 CTAs
    mha_hmma_kernel<<<grid, NTH, SMEM_TOTAL>>>(k, src, dest, out);
}

// round 4
// speedup vs baseline: 2.2351x; 1.1569x over previous
#include <cuda_runtime.h>
#include <cuda_bf16.h>
#include <cstdint>

#define L_DIM 2048
#define D_DIM 64
#define N_BH 32
#define ROWS 256
#define JT 64
#define NJT (L_DIM / JT)     // 32
#define NTH 256

// smem layout (bytes)
#define OFF_AH 0
#define OFF_AL 32768
#define OFF_BHI(b) (65536 + (b) * 16384)
#define OFF_BLO(b) (65536 + (b) * 16384 + 8192)
#define SMEM_TOTAL 98304

#define NELEM (N_BH * L_DIM * D_DIM)    // 4,194,304

// Pre-converted, pre-column-permuted bf16 operands (8 MB each)
__device__ __align__(16) __nv_bfloat16 g_Ah[NELEM];
__device__ __align__(16) __nv_bfloat16 g_Al[NELEM];
__device__ __align__(16) __nv_bfloat16 g_Bh[NELEM];
__device__ __align__(16) __nv_bfloat16 g_Bl[NELEM];

__device__ __forceinline__ uint32_t smem_u32(const void* p) {
    uint32_t a;
    asm("{ .reg .u64 t; cvta.to.shared.u64 t, %1; cvt.u32.u64 %0, t; }" : "=r"(a) : "l"(p));
    return a;
}
__device__ __forceinline__ float lg2f(float x) {
    float y; asm("lg2.approx.f32 %0, %1;" : "=f"(y) : "f"(x)); return y;
}
__device__ __forceinline__ float ex2f(float x) {
    float y; asm("ex2.approx.f32 %0, %1;" : "=f"(y) : "f"(x)); return y;
}
__device__ __forceinline__ float pow23(float a) {
    float x = fmaxf(a, 0.0f) + 1e-12f;
    return ex2f(lg2f(x) * 0.666666667f);
}
__device__ __forceinline__ void ldsm4(uint32_t* r, uint32_t addr) {
    asm volatile("ldmatrix.sync.aligned.m8n8.x4.shared.b16 {%0,%1,%2,%3}, [%4];"
                 : "=r"(r[0]), "=r"(r[1]), "=r"(r[2]), "=r"(r[3]) : "r"(addr));
}
__device__ __forceinline__ void mma16816(float* c, const uint32_t* a, const uint32_t* b) {
    asm volatile(
        "mma.sync.aligned.m16n8k16.row.col.f32.bf16.bf16.f32 "
        "{%0,%1,%2,%3}, {%4,%5,%6,%7}, {%8,%9}, {%0,%1,%2,%3};"
        : "+f"(c[0]), "+f"(c[1]), "+f"(c[2]), "+f"(c[3])
        : "r"(a[0]), "r"(a[1]), "r"(a[2]), "r"(a[3]), "r"(b[0]), "r"(b[1]));
}
__device__ __forceinline__ void cpa16(uint32_t dst, const void* src) {
    asm volatile("cp.async.cg.shared.global [%0], [%1], 16;" :: "r"(dst), "l"(src) : "memory");
}
__device__ __forceinline__ void cpa_commit() {
    asm volatile("cp.async.commit_group;" ::: "memory");
}
__device__ __forceinline__ void cpa_wait1() {
    asm volatile("cp.async.wait_group 1;" ::: "memory");
}

// Pre-pass: scale by sqrt(w+eps), split bf16 hi + residual lo, store with the
// SW128 column permutation baked in: elem e of a row lands at e ^ ((row&7)<<3).
__global__ void __launch_bounds__(NTH)
prep_kernel(const float* __restrict__ kin, const float* __restrict__ src,
            const float* __restrict__ dst)
{
    int gid = blockIdx.x * NTH + threadIdx.x;    // 0 .. 262143
    int rowg = gid >> 2;                         // bh*2048 + row
    int q = gid & 3;                             // 16-col quarter
    int row = rowg & (L_DIM - 1);
    float s = sqrtf(src[rowg] + 1e-12f);
    float d = sqrtf(dst[rowg] + 1e-12f);
    const float* kp = kin + (size_t)rowg * D_DIM + q * 16;
    const int perm = (row & 7) << 3;
    const size_t rbase = (size_t)rowg * D_DIM;

    #pragma unroll
    for (int g = 0; g < 2; ++g) {
        float x[8];
        float4 v0 = *(const float4*)(kp + g * 8);
        float4 v1 = *(const float4*)(kp + g * 8 + 4);
        x[0] = v0.x; x[1] = v0.y; x[2] = v0.z; x[3] = v0.w;
        x[4] = v1.x; x[5] = v1.y; x[6] = v1.z; x[7] = v1.w;
        uint32_t ah[4], al[4], bh[4], bl[4];
        #pragma unroll
        for (int p = 0; p < 4; ++p) {
            float xa0 = x[2 * p] * s, xa1 = x[2 * p + 1] * s;
            __nv_bfloat16 h0 = __float2bfloat16(xa0), h1 = __float2bfloat16(xa1);
            __nv_bfloat16 l0 = __float2bfloat16(xa0 - __bfloat162float(h0));
            __nv_bfloat16 l1 = __float2bfloat16(xa1 - __bfloat162float(h1));
            __nv_bfloat162 hp = __halves2bfloat162(h0, h1);
            __nv_bfloat162 lp = __halves2bfloat162(l0, l1);
            ah[p] = *(uint32_t*)&hp; al[p] = *(uint32_t*)&lp;
            float xb0 = x[2 * p] * d, xb1 = x[2 * p + 1] * d;
            __nv_bfloat16 g0 = __float2bfloat16(xb0), g1 = __float2bfloat16(xb1);
            __nv_bfloat16 m0 = __float2bfloat16(xb0 - __bfloat162float(g0));
            __nv_bfloat16 m1 = __float2bfloat16(xb1 - __bfloat162float(g1));
            __nv_bfloat162 gp = __halves2bfloat162(g0, g1);
            __nv_bfloat162 mp = __halves2bfloat162(m0, m1);
            bh[p] = *(uint32_t*)&gp; bl[p] = *(uint32_t*)&mp;
        }
        int edst = (q * 16 + g * 8) ^ perm;      // aligned 8-elem group
        *(uint4*)(g_Ah + rbase + edst) = make_uint4(ah[0], ah[1], ah[2], ah[3]);
        *(uint4*)(g_Al + rbase + edst) = make_uint4(al[0], al[1], al[2], al[3]);
        *(uint4*)(g_Bh + rbase + edst) = make_uint4(bh[0], bh[1], bh[2], bh[3]);
        *(uint4*)(g_Bl + rbase + edst) = make_uint4(bl[0], bl[1], bl[2], bl[3]);
    }
}

__device__ __forceinline__ void copyB(uint32_t sbase, int buf, size_t bbase, int jt, int tid)
{
    #pragma unroll
    for (int it = 0; it < 2; ++it) {
        int idx = tid + it * NTH;               // 0..511
        int row = idx >> 3, seg = idx & 7;
        size_t goff = bbase + (size_t)(jt * JT + row) * D_DIM + seg * 8;
        uint32_t soff = (uint32_t)(row * 128 + seg * 16);
        cpa16(sbase + OFF_BHI(buf) + soff, g_Bh + goff);
        cpa16(sbase + OFF_BLO(buf) + soff, g_Bl + goff);
    }
}

__global__ void __launch_bounds__(NTH, 2)
mha_hmma2(float* __restrict__ out)
{
    extern __shared__ char smem[];
    const uint32_t sbase = smem_u32(smem);
    const int tid = threadIdx.x;
    const int warp = tid >> 5;
    const int lane = tid & 31;
    const int q = lane & 3;
    const int bh = blockIdx.y;
    const int i0 = blockIdx.x * ROWS;

    const size_t abase = ((size_t)bh * L_DIM + i0) * D_DIM;
    const size_t bbase = (size_t)bh * L_DIM * D_DIM;

    // A tiles (hi+lo, 256 rows): 8 chunks/thread/array
    #pragma unroll
    for (int it = 0; it < 8; ++it) {
        int idx = tid + it * NTH;               // 0..2047
        int row = idx >> 3, seg = idx & 7;
        size_t goff = abase + (size_t)row * D_DIM + seg * 8;
        uint32_t soff = (uint32_t)(row * 128 + seg * 16);
        cpa16(sbase + OFF_AH + soff, g_Ah + goff);
        cpa16(sbase + OFF_AL + soff, g_Al + goff);
    }
    copyB(sbase, 0, bbase, 0, tid);
    cpa_commit();                                // G0 = A + B(0)
    copyB(sbase, 1, bbase, 1, tid);
    cpa_commit();                                // G1 = B(1)

    // ldmatrix lane geometry (identical mapping to R3, two m-frags per warp)
    const int rb  = warp * 32;
    const int ar0 = rb + ((lane >> 3) & 1) * 8 + (lane & 7);
    const int ar1 = ar0 + 16;
    const int a_kb = ((lane >> 4) & 1) * 16;
    const int ax   = (ar0 & 7) << 4;             // same for ar1 (+16)
    const int br   = ((lane >> 4) & 1) * 8 + (lane & 7);
    const int b_kb = ((lane >> 3) & 1) * 16;
    const int bx   = (br & 7) << 4;

    const uint32_t AH = sbase + OFF_AH, AL = sbase + OFF_AL;

    float c_up[2] = {0.0f, 0.0f}, c_dn[2] = {0.0f, 0.0f};

    for (int jt = 0; jt < NJT; ++jt) {
        cpa_wait1();
        __syncthreads();                         // buffer jt&1 ready for all warps
        const uint32_t BH = sbase + OFF_BHI(jt & 1);
        const uint32_t BL = sbase + OFF_BLO(jt & 1);

        float acc[2][8][4];
        #pragma unroll
        for (int m = 0; m < 2; ++m)
            #pragma unroll
            for (int n = 0; n < 8; ++n)
                #pragma unroll
                for (int c = 0; c < 4; ++c) acc[m][n][c] = 0.0f;

        #pragma unroll
        for (int ks = 0; ks < 4; ++ks) {
            const int ka = ((ks * 32) | a_kb) ^ ax;
            uint32_t ah0[4], al0[4], ah1[4], al1[4];
            ldsm4(ah0, AH + ar0 * 128 + ka);
            ldsm4(ah1, AH + ar1 * 128 + ka);
            ldsm4(al0, AL + ar0 * 128 + ka);
            ldsm4(al1, AL + ar1 * 128 + ka);
            const int kb2 = ((ks * 32) | b_kb) ^ bx;
            #pragma unroll
            for (int cg = 0; cg < 4; ++cg) {
                const uint32_t bo = (uint32_t)((cg * 16 + br) * 128 + kb2);
                uint32_t bhf[4], blf[4];
                ldsm4(bhf, BH + bo);
                ldsm4(blf, BL + bo);
                mma16816(acc[0][2 * cg],     ah0, bhf);
                mma16816(acc[0][2 * cg + 1], ah0, bhf + 2);
                mma16816(acc[1][2 * cg],     ah1, bhf);
                mma16816(acc[1][2 * cg + 1], ah1, bhf + 2);
                mma16816(acc[0][2 * cg],     al0, bhf);
                mma16816(acc[0][2 * cg + 1], al0, bhf + 2);
                mma16816(acc[1][2 * cg],     al1, bhf);
                mma16816(acc[1][2 * cg + 1], al1, bhf + 2);
                mma16816(acc[0][2 * cg],     ah0, blf);
                mma16816(acc[0][2 * cg + 1], ah0, blf + 2);
                mma16816(acc[1][2 * cg],     ah1, blf);
                mma16816(acc[1][2 * cg + 1], ah1, blf + 2);
            }
        }

        __syncthreads();                         // all reads of buf[jt&1] done
        if (jt + 2 < NJT) copyB(sbase, jt & 1, bbase, jt + 2, tid);
        cpa_commit();                            // constant pipeline depth (may be empty)

        // epilogue: pow(2/3) on MUFU, 4-lane segmented scan, carry, mask, store
        #pragma unroll
        for (int m = 0; m < 2; ++m) {
            const int iu = i0 + rb + m * 16 + (lane >> 2);
            const int idn = iu + 8;
            float* oru = out + ((size_t)bh * L_DIM + iu) * L_DIM;
            float* ord = oru + 8 * L_DIM;
            #pragma unroll
            for (int nb = 0; nb < 8; ++nb) {
                const int j0 = jt * JT + nb * 8 + q * 2;
                {
                    float y0 = pow23(acc[m][nb][0]);
                    float y1 = pow23(acc[m][nb][1]);
                    float v = y0 + y1, sc = v;
                    float u1 = __shfl_up_sync(0xffffffffu, sc, 1, 4); if (q >= 1) sc += u1;
                    float u2 = __shfl_up_sync(0xffffffffu, sc, 2, 4); if (q >= 2) sc += u2;
                    float tot = __shfl_sync(0xffffffffu, sc, 3, 4);
                    float base = c_up[m] + (sc - v);
                    float2 o;
                    o.x = (j0     >= iu) ? base + y0 : 0.0f;
                    o.y = (j0 + 1 >= iu) ? base + v  : 0.0f;
                    *(float2*)(oru + j0) = o;
                    c_up[m] += tot;
                }
                {
                    float y0 = pow23(acc[m][nb][2]);
                    float y1 = pow23(acc[m][nb][3]);
                    float v = y0 + y1, sc = v;
                    float u1 = __shfl_up_sync(0xffffffffu, sc, 1, 4); if (q >= 1) sc += u1;
                    float u2 = __shfl_up_sync(0xffffffffu, sc, 2, 4); if (q >= 2) sc += u2;
                    float tot = __shfl_sync(0xffffffffu, sc, 3, 4);
                    float base = c_dn[m] + (sc - v);
                    float2 o;
                    o.x = (j0     >= idn) ? base + y0 : 0.0f;
                    o.y = (j0 + 1 >= idn) ? base + v  : 0.0f;
                    *(float2*)(ord + j0) = o;
                    c_dn[m] += tot;
                }
            }
        }
    }
}

extern "C" void kernel_launch(void* const* d_in, const int* in_sizes, int n_in,
                              void* d_out, int out_size) {
    const float* k    = (const float*)d_in[0];
    const float* src  = (const float*)d_in[1];
    const float* dest = (const float*)d_in[2];
    float* out = (float*)d_out;

    prep_kernel<<<(N_BH * L_DIM * 4) / NTH, NTH>>>(k, src, dest);

    cudaFuncSetAttribute(mha_hmma2,
                         cudaFuncAttributeMaxDynamicSharedMemorySize, SMEM_TOTAL);
    dim3 grid(L_DIM / ROWS, N_BH);   // 8 x 32 = 256 CTAs
    mha_hmma2<<<grid, NTH, SMEM_TOTAL>>>(out);
}

// round 5
// speedup vs baseline: 2.8693x; 1.2838x over previous
#include <cuda_runtime.h>
#include <cuda_fp16.h>
#include <cstdint>

#define L_DIM 2048
#define D_DIM 64
#define N_BH 32
#define ROWS 256
#define JT 128
#define NJT (L_DIM / JT)     // 16
#define NTH 256

#define OFF_A 0
#define OFF_B(b) (32768 + (b) * 16384)
#define SMEM_TOTAL 65536

#define NELEM (N_BH * L_DIM * D_DIM)

// fp16 operands, pre-scaled and pre-column-permuted for SW128 ldmatrix
__device__ __align__(16) __half g_A[NELEM];
__device__ __align__(16) __half g_B[NELEM];

__device__ __forceinline__ uint32_t smem_u32(const void* p) {
    uint32_t a;
    asm("{ .reg .u64 t; cvta.to.shared.u64 t, %1; cvt.u32.u64 %0, t; }" : "=r"(a) : "l"(p));
    return a;
}
__device__ __forceinline__ float lg2f(float x) {
    float y; asm("lg2.approx.f32 %0, %1;" : "=f"(y) : "f"(x)); return y;
}
__device__ __forceinline__ float ex2f(float x) {
    float y; asm("ex2.approx.f32 %0, %1;" : "=f"(y) : "f"(x)); return y;
}
// MUFU-pipe (relu(a)+1e-12)^(2/3)
__device__ __forceinline__ float pow23_mufu(float a) {
    float x = fmaxf(a, 0.0f) + 1e-12f;
    return ex2f(lg2f(x) * 0.666666667f);
}
// FMA-pipe version: rcbrt bit-seed + 2 Newton iterations (no MUFU)
__device__ __forceinline__ float pow23_fma(float a) {
    float x = fmaxf(a, 0.0f) + 1e-12f;
    float w = __int_as_float(0x54A2FC96 - (__float_as_int(x) / 3));
    float t = x * w;
    float u = fmaf(-(1.0f / 3.0f), t * w * w, 4.0f / 3.0f);
    w = w * u;
    t = x * w;
    u = fmaf(-(1.0f / 3.0f), t * w * w, 4.0f / 3.0f);
    return t * u;
}
__device__ __forceinline__ void ldsm4(uint32_t* r, uint32_t addr) {
    asm volatile("ldmatrix.sync.aligned.m8n8.x4.shared.b16 {%0,%1,%2,%3}, [%4];"
                 : "=r"(r[0]), "=r"(r[1]), "=r"(r[2]), "=r"(r[3]) : "r"(addr));
}
__device__ __forceinline__ void mma16816(float* c, const uint32_t* a, const uint32_t* b) {
    asm volatile(
        "mma.sync.aligned.m16n8k16.row.col.f32.f16.f16.f32 "
        "{%0,%1,%2,%3}, {%4,%5,%6,%7}, {%8,%9}, {%0,%1,%2,%3};"
        : "+f"(c[0]), "+f"(c[1]), "+f"(c[2]), "+f"(c[3])
        : "r"(a[0]), "r"(a[1]), "r"(a[2]), "r"(a[3]), "r"(b[0]), "r"(b[1]));
}
__device__ __forceinline__ void cpa16(uint32_t dst, const void* src) {
    asm volatile("cp.async.cg.shared.global [%0], [%1], 16;" :: "r"(dst), "l"(src) : "memory");
}
__device__ __forceinline__ void cpa_commit() {
    asm volatile("cp.async.commit_group;" ::: "memory");
}
__device__ __forceinline__ void cpa_wait1() {
    asm volatile("cp.async.wait_group 1;" ::: "memory");
}

// Pre-pass: k*sqrt(src+eps) -> g_A (fp16), k*sqrt(dest+eps) -> g_B (fp16),
// with the SW128 column permutation baked in: elem e -> e ^ ((row&7)<<3).
__global__ void __launch_bounds__(NTH)
prep_kernel(const float* __restrict__ kin, const float* __restrict__ src,
            const float* __restrict__ dst)
{
    int gid = blockIdx.x * NTH + threadIdx.x;    // 0 .. 262143
    int rowg = gid >> 2;
    int q = gid & 3;
    int row = rowg & (L_DIM - 1);
    float s = sqrtf(src[rowg] + 1e-12f);
    float d = sqrtf(dst[rowg] + 1e-12f);
    const float* kp = kin + (size_t)rowg * D_DIM + q * 16;
    const int perm = (row & 7) << 3;
    const size_t rbase = (size_t)rowg * D_DIM;

    #pragma unroll
    for (int g = 0; g < 2; ++g) {
        float4 v0 = *(const float4*)(kp + g * 8);
        float4 v1 = *(const float4*)(kp + g * 8 + 4);
        __half2 a0 = __floats2half2_rn(v0.x * s, v0.y * s);
        __half2 a1 = __floats2half2_rn(v0.z * s, v0.w * s);
        __half2 a2 = __floats2half2_rn(v1.x * s, v1.y * s);
        __half2 a3 = __floats2half2_rn(v1.z * s, v1.w * s);
        __half2 b0 = __floats2half2_rn(v0.x * d, v0.y * d);
        __half2 b1 = __floats2half2_rn(v0.z * d, v0.w * d);
        __half2 b2 = __floats2half2_rn(v1.x * d, v1.y * d);
        __half2 b3 = __floats2half2_rn(v1.z * d, v1.w * d);
        int edst = (q * 16 + g * 8) ^ perm;
        *(uint4*)(g_A + rbase + edst) = make_uint4(*(uint32_t*)&a0, *(uint32_t*)&a1,
                                                   *(uint32_t*)&a2, *(uint32_t*)&a3);
        *(uint4*)(g_B + rbase + edst) = make_uint4(*(uint32_t*)&b0, *(uint32_t*)&b1,
                                                   *(uint32_t*)&b2, *(uint32_t*)&b3);
    }
}

__device__ __forceinline__ void copyB(uint32_t sbase, int buf, size_t bbase, int jt, int tid)
{
    #pragma unroll
    for (int it = 0; it < 4; ++it) {
        int idx = tid + it * NTH;               // 0..1023
        int row = idx >> 3, seg = idx & 7;
        cpa16(sbase + OFF_B(buf) + (uint32_t)(row * 128 + seg * 16),
              g_B + bbase + (size_t)(jt * JT + row) * D_DIM + seg * 8);
    }
}

__global__ void __launch_bounds__(NTH, 2)
mha_fp16(float* __restrict__ out)
{
    extern __shared__ char smem[];
    const uint32_t sbase = smem_u32(smem);
    const int tid = threadIdx.x;
    const int warp = tid >> 5;
    const int lane = tid & 31;
    const int q = lane & 3;
    const int bh = blockIdx.y;
    const int i0 = blockIdx.x * ROWS;

    const size_t abase = ((size_t)bh * L_DIM + i0) * D_DIM;
    const size_t bbase = (size_t)bh * L_DIM * D_DIM;

    // A tile (256 rows x 128B fp16)
    #pragma unroll
    for (int it = 0; it < 8; ++it) {
        int idx = tid + it * NTH;
        int row = idx >> 3, seg = idx & 7;
        cpa16(sbase + OFF_A + (uint32_t)(row * 128 + seg * 16),
              g_A + abase + (size_t)row * D_DIM + seg * 8);
    }
    copyB(sbase, 0, bbase, 0, tid);
    cpa_commit();                 // G0 = A + B(0)
    copyB(sbase, 1, bbase, 1, tid);
    cpa_commit();                 // G1 = B(1)

    // lane geometry
    const int rb  = warp * 32;
    const int ar0 = rb + ((lane >> 3) & 1) * 8 + (lane & 7);
    const int ar1 = ar0 + 16;
    const int a_kb = ((lane >> 4) & 1) * 16;
    const int ax   = (ar0 & 7) << 4;
    const int br   = ((lane >> 4) & 1) * 8 + (lane & 7);
    const int b_kb = ((lane >> 3) & 1) * 16;
    const int bx   = (br & 7) << 4;

    cpa_wait1();                  // G0 done -> A ready
    __syncthreads();

    // hoist A fragments into registers (reused across all 16 j-tiles)
    uint32_t afr0[4][4], afr1[4][4];
    #pragma unroll
    for (int ks = 0; ks < 4; ++ks) {
        const int ka = ((ks * 32) | a_kb) ^ ax;
        ldsm4(afr0[ks], sbase + OFF_A + ar0 * 128 + ka);
        ldsm4(afr1[ks], sbase + OFF_A + ar1 * 128 + ka);
    }

    float c_up[2] = {0.0f, 0.0f}, c_dn[2] = {0.0f, 0.0f};

    for (int jt = 0; jt < NJT; ++jt) {
        if (jt) { cpa_wait1(); __syncthreads(); }   // buffer jt&1 ready
        const uint32_t B = sbase + OFF_B(jt & 1);

        #pragma unroll
        for (int h = 0; h < 2; ++h) {
            float acc[2][8][4];
            #pragma unroll
            for (int m = 0; m < 2; ++m)
                #pragma unroll
                for (int n = 0; n < 8; ++n)
                    #pragma unroll
                    for (int c = 0; c < 4; ++c) acc[m][n][c] = 0.0f;

            #pragma unroll
            for (int ks = 0; ks < 4; ++ks) {
                const int kb2 = ((ks * 32) | b_kb) ^ bx;
                #pragma unroll
                for (int cgl = 0; cgl < 4; ++cgl) {
                    const int cg = h * 4 + cgl;
                    uint32_t bf[4];
                    ldsm4(bf, B + (uint32_t)((cg * 16 + br) * 128 + kb2));
                    mma16816(acc[0][2 * cgl],     afr0[ks], bf);
                    mma16816(acc[0][2 * cgl + 1], afr0[ks], bf + 2);
                    mma16816(acc[1][2 * cgl],     afr1[ks], bf);
                    mma16816(acc[1][2 * cgl + 1], afr1[ks], bf + 2);
                }
            }

            if (h == 1) {           // B buffer fully consumed -> prefetch jt+2
                __syncthreads();
                if (jt + 2 < NJT) copyB(sbase, jt & 1, bbase, jt + 2, tid);
                cpa_commit();
            }

            // epilogue for cols [jt*128 + h*64, +64)
            #pragma unroll
            for (int m = 0; m < 2; ++m) {
                const int iu = i0 + rb + m * 16 + (lane >> 2);
                const int idn = iu + 8;
                float* oru = out + ((size_t)bh * L_DIM + iu) * L_DIM;
                float* ord = oru + 8 * L_DIM;
                #pragma unroll
                for (int nb = 0; nb < 8; ++nb) {
                    const int j0 = jt * JT + h * 64 + nb * 8 + q * 2;
                    float y0, y1, z0, z1;
                    if (nb & 1) {
                        y0 = pow23_fma(acc[m][nb][0]); y1 = pow23_fma(acc[m][nb][1]);
                        z0 = pow23_fma(acc[m][nb][2]); z1 = pow23_fma(acc[m][nb][3]);
                    } else {
                        y0 = pow23_mufu(acc[m][nb][0]); y1 = pow23_mufu(acc[m][nb][1]);
                        z0 = pow23_mufu(acc[m][nb][2]); z1 = pow23_mufu(acc[m][nb][3]);
                    }
                    {
                        float v = y0 + y1, sc = v;
                        float u1 = __shfl_up_sync(0xffffffffu, sc, 1, 4); if (q >= 1) sc += u1;
                        float u2 = __shfl_up_sync(0xffffffffu, sc, 2, 4); if (q >= 2) sc += u2;
                        float tot = __shfl_sync(0xffffffffu, sc, 3, 4);
                        float base = c_up[m] + (sc - v);
                        float2 o;
                        o.x = (j0     >= iu) ? base + y0 : 0.0f;
                        o.y = (j0 + 1 >= iu) ? base + v  : 0.0f;
                        *(float2*)(oru + j0) = o;
                        c_up[m] += tot;
                    }
                    {
                        float v = z0 + z1, sc = v;
                        float u1 = __shfl_up_sync(0xffffffffu, sc, 1, 4); if (q >= 1) sc += u1;
                        float u2 = __shfl_up_sync(0xffffffffu, sc, 2, 4); if (q >= 2) sc += u2;
                        float tot = __shfl_sync(0xffffffffu, sc, 3, 4);
                        float base = c_dn[m] + (sc - v);
                        float2 o;
                        o.x = (j0     >= idn) ? base + z0 : 0.0f;
                        o.y = (j0 + 1 >= idn) ? base + v  : 0.0f;
                        *(float2*)(ord + j0) = o;
                        c_dn[m] += tot;
                    }
                }
            }
        }
    }
}

extern "C" void kernel_launch(void* const* d_in, const int* in_sizes, int n_in,
                              void* d_out, int out_size) {
    const float* k    = (const float*)d_in[0];
    const float* src  = (const float*)d_in[1];
    const float* dest = (const float*)d_in[2];
    float* out = (float*)d_out;

    prep_kernel<<<(N_BH * L_DIM * 4) / NTH, NTH>>>(k, src, dest);

    cudaFuncSetAttribute(mha_fp16,
                         cudaFuncAttributeMaxDynamicSharedMemorySize, SMEM_TOTAL);
    dim3 grid(L_DIM / ROWS, N_BH);   // 8 x 32 = 256 CTAs
    mha_fp16<<<grid, NTH, SMEM_TOTAL>>>(out);
}